// round 1
// baseline (speedup 1.0000x reference)
#include <cuda_runtime.h>

// Problem constants
#define NB 4
#define NN 1024
#define MM 1024
#define CC 768
#define HH 12
#define DD 64
#define ROWS (NB * NN)        // 4096
#define ATT_SCALE 0.125f      // 64^-0.5

// Scratch (static device arrays — allocation-free per harness rules)
__device__ float g_Q[NB * NN * CC];
__device__ float g_K[NB * MM * CC];
__device__ float g_V[NB * MM * CC];
__device__ float g_O[NB * NN * CC];

// ---------------------------------------------------------------------------
// NT GEMM: out[r][c] = sum_k A[r][k] * W[c][k]  (+ rowbias[r]) (+ colbias[c])
// 64x64 tile per block, 256 threads, 4x4 register micro-tile, BK=16.
// ---------------------------------------------------------------------------
template <bool ROWB, bool COLB>
__global__ __launch_bounds__(256) void gemm_nt(
    const float* __restrict__ A, const float* __restrict__ W,
    const float* __restrict__ rowbias, const float* __restrict__ colbias,
    float* __restrict__ out)
{
    __shared__ float As[16][64];
    __shared__ float Bs[16][64];

    const int tid = threadIdx.x;
    const int tx = tid & 15;       // 0..15 -> output col group
    const int ty = tid >> 4;       // 0..15 -> output row group
    const int row0 = blockIdx.x * 64;
    const int col0 = blockIdx.y * 64;

    const int lm  = tid >> 2;      // 0..63 : tile row being loaded
    const int lk4 = tid & 3;       // 0..3  : float4 index within BK=16

    const float* Ap = A + (size_t)(row0 + lm) * CC + lk4 * 4;
    const float* Wp = W + (size_t)(col0 + lm) * CC + lk4 * 4;

    float acc[4][4] = {};

    for (int k0 = 0; k0 < CC; k0 += 16) {
        float4 av = *(const float4*)(Ap + k0);
        float4 wv = *(const float4*)(Wp + k0);
        As[lk4 * 4 + 0][lm] = av.x;
        As[lk4 * 4 + 1][lm] = av.y;
        As[lk4 * 4 + 2][lm] = av.z;
        As[lk4 * 4 + 3][lm] = av.w;
        Bs[lk4 * 4 + 0][lm] = wv.x;
        Bs[lk4 * 4 + 1][lm] = wv.y;
        Bs[lk4 * 4 + 2][lm] = wv.z;
        Bs[lk4 * 4 + 3][lm] = wv.w;
        __syncthreads();

        #pragma unroll
        for (int k = 0; k < 16; k++) {
            float4 a4 = *(const float4*)&As[k][ty * 4];
            float4 b4 = *(const float4*)&Bs[k][tx * 4];
            float af[4] = {a4.x, a4.y, a4.z, a4.w};
            float bf[4] = {b4.x, b4.y, b4.z, b4.w};
            #pragma unroll
            for (int i = 0; i < 4; i++)
                #pragma unroll
                for (int j = 0; j < 4; j++)
                    acc[i][j] += af[i] * bf[j];
        }
        __syncthreads();
    }

    #pragma unroll
    for (int i = 0; i < 4; i++) {
        const int r = row0 + ty * 4 + i;
        const float rb = ROWB ? rowbias[r] : 0.0f;
        float4 ov;
        const int c = col0 + tx * 4;
        ov.x = acc[i][0] + rb + (COLB ? colbias[c + 0] : 0.0f);
        ov.y = acc[i][1] + rb + (COLB ? colbias[c + 1] : 0.0f);
        ov.z = acc[i][2] + rb + (COLB ? colbias[c + 2] : 0.0f);
        ov.w = acc[i][3] + rb + (COLB ? colbias[c + 3] : 0.0f);
        *(float4*)(out + (size_t)r * CC + c) = ov;
    }
}

// ---------------------------------------------------------------------------
// Flash attention over one (b, h, 64-query tile).
// grid: (NN/64, NB*HH), 256 threads.
// Smem: Qs[d][r] 64x64, Ks[d][c] 64x64, Vs[m][d] 64x64, St[c][r] 64x68 (S^T),
//       alpha/rowmax/rowsum[64].
// ---------------------------------------------------------------------------
#define STS 68   // padded stride for S^T: stride%32==4 (bank spread), 16B aligned

#define ATTN_SMEM_FLOATS (3 * 64 * 64 + 64 * STS + 3 * 64)
#define ATTN_SMEM_BYTES (ATTN_SMEM_FLOATS * 4)

__global__ __launch_bounds__(256) void attn_kernel()
{
    extern __shared__ float sm[];
    float* Qs   = sm;                    // [64][64], Qs[d*64 + r]
    float* Ks   = Qs + 64 * 64;          // [64][64], Ks[d*64 + c]
    float* Vs   = Ks + 64 * 64;          // [64][64], Vs[m*64 + d]
    float* St   = Vs + 64 * 64;          // [64][STS], St[c*STS + r]  (S transposed)
    float* alph = St + 64 * STS;
    float* rmax = alph + 64;
    float* rsum = rmax + 64;

    const int tid = threadIdx.x;
    const int tx = tid & 15;
    const int ty = tid >> 4;
    const int n0 = blockIdx.x * 64;
    const int b  = blockIdx.y / HH;
    const int h  = blockIdx.y % HH;

    const size_t baseQ  = ((size_t)(b * NN + n0)) * CC + h * DD;
    const size_t baseKV = ((size_t)(b * MM)) * CC + h * DD;

    // Load Q tile transposed: Qs[d][r]
    for (int f = tid; f < 1024; f += 256) {
        const int r = f >> 4, d4 = f & 15;
        float4 v = *(const float4*)(g_Q + baseQ + (size_t)r * CC + d4 * 4);
        Qs[(d4 * 4 + 0) * 64 + r] = v.x;
        Qs[(d4 * 4 + 1) * 64 + r] = v.y;
        Qs[(d4 * 4 + 2) * 64 + r] = v.z;
        Qs[(d4 * 4 + 3) * 64 + r] = v.w;
    }
    if (tid < 64) { rmax[tid] = -1e30f; rsum[tid] = 0.0f; }

    float acc[4][4] = {};
    __syncthreads();

    for (int m0 = 0; m0 < MM; m0 += 64) {
        // Load K tile transposed (Ks[d][c]) and V tile natural (Vs[m][d])
        for (int f = tid; f < 1024; f += 256) {
            const int r = f >> 4, d4 = f & 15;
            const size_t g = baseKV + (size_t)(m0 + r) * CC + d4 * 4;
            float4 kv = *(const float4*)(g_K + g);
            Ks[(d4 * 4 + 0) * 64 + r] = kv.x;
            Ks[(d4 * 4 + 1) * 64 + r] = kv.y;
            Ks[(d4 * 4 + 2) * 64 + r] = kv.z;
            Ks[(d4 * 4 + 3) * 64 + r] = kv.w;
            float4 vv = *(const float4*)(g_V + g);
            *(float4*)&Vs[r * 64 + d4 * 4] = vv;
        }
        __syncthreads();

        // S = (Q K^T) * scale, stored transposed into St[c][r]
        {
            float s[4][4] = {};
            #pragma unroll
            for (int d = 0; d < 64; d++) {
                float4 a4 = *(const float4*)&Qs[d * 64 + ty * 4];
                float4 b4 = *(const float4*)&Ks[d * 64 + tx * 4];
                float af[4] = {a4.x, a4.y, a4.z, a4.w};
                float bf[4] = {b4.x, b4.y, b4.z, b4.w};
                #pragma unroll
                for (int i = 0; i < 4; i++)
                    #pragma unroll
                    for (int j = 0; j < 4; j++)
                        s[i][j] += af[i] * bf[j];
            }
            #pragma unroll
            for (int i = 0; i < 4; i++)
                #pragma unroll
                for (int j = 0; j < 4; j++)
                    St[(tx * 4 + j) * STS + (ty * 4 + i)] = s[i][j] * ATT_SCALE;
        }
        __syncthreads();

        // Online softmax row pass: thread t owns row t (reads column t of St)
        if (tid < 64) {
            const int r = tid;
            const float mo = rmax[r];
            float ml = -1e30f;
            #pragma unroll 8
            for (int m = 0; m < 64; m++) ml = fmaxf(ml, St[m * STS + r]);
            const float mn = fmaxf(mo, ml);
            const float al = __expf(mo - mn);
            float ssum = 0.0f;
            #pragma unroll 8
            for (int m = 0; m < 64; m++) {
                const float p = __expf(St[m * STS + r] - mn);
                St[m * STS + r] = p;
                ssum += p;
            }
            rsum[r] = rsum[r] * al + ssum;
            rmax[r] = mn;
            alph[r] = al;
        }
        __syncthreads();

        // O = O * alpha(row) + P @ V
        {
            float al[4];
            #pragma unroll
            for (int i = 0; i < 4; i++) al[i] = alph[ty * 4 + i];
            #pragma unroll
            for (int i = 0; i < 4; i++)
                #pragma unroll
                for (int j = 0; j < 4; j++)
                    acc[i][j] *= al[i];

            #pragma unroll
            for (int m = 0; m < 64; m++) {
                float4 p4 = *(const float4*)&St[m * STS + ty * 4];
                float4 v4 = *(const float4*)&Vs[m * 64 + tx * 4];
                float pf[4] = {p4.x, p4.y, p4.z, p4.w};
                float vf[4] = {v4.x, v4.y, v4.z, v4.w};
                #pragma unroll
                for (int i = 0; i < 4; i++)
                    #pragma unroll
                    for (int j = 0; j < 4; j++)
                        acc[i][j] += pf[i] * vf[j];
            }
        }
        __syncthreads();
    }

    // Normalize and write out (same layout as Q: [b, n, h*D + d])
    float inv[4];
    #pragma unroll
    for (int i = 0; i < 4; i++) inv[i] = 1.0f / rsum[ty * 4 + i];
    #pragma unroll
    for (int i = 0; i < 4; i++) {
        const size_t o = baseQ + (size_t)(ty * 4 + i) * CC + tx * 4;
        float4 ov;
        ov.x = acc[i][0] * inv[i];
        ov.y = acc[i][1] * inv[i];
        ov.z = acc[i][2] * inv[i];
        ov.w = acc[i][3] * inv[i];
        *(float4*)(g_O + o) = ov;
    }
}

// ---------------------------------------------------------------------------
// Launch
// ---------------------------------------------------------------------------
extern "C" void kernel_launch(void* const* d_in, const int* in_sizes, int n_in,
                              void* d_out, int out_size)
{
    const float* x  = (const float*)d_in[0];
    const float* y  = (const float*)d_in[1];
    const float* yw = (const float*)d_in[2];
    const float* Wq = (const float*)d_in[3];
    const float* Wk = (const float*)d_in[4];
    const float* Wv = (const float*)d_in[5];
    const float* Wp = (const float*)d_in[6];
    const float* bp = (const float*)d_in[7];
    float* out = (float*)d_out;

    float *Qp, *Kp, *Vp, *Op;
    cudaGetSymbolAddress((void**)&Qp, g_Q);
    cudaGetSymbolAddress((void**)&Kp, g_K);
    cudaGetSymbolAddress((void**)&Vp, g_V);
    cudaGetSymbolAddress((void**)&Op, g_O);

    cudaFuncSetAttribute(attn_kernel,
                         cudaFuncAttributeMaxDynamicSharedMemorySize,
                         ATTN_SMEM_BYTES);

    const dim3 gproj(ROWS / 64, CC / 64);

    // Projections: Q = x Wq^T ; K = y Wk^T + yw[r] ; V = y Wv^T
    gemm_nt<false, false><<<gproj, 256>>>(x, Wq, nullptr, nullptr, Qp);
    gemm_nt<true,  false><<<gproj, 256>>>(y, Wk, yw,      nullptr, Kp);
    gemm_nt<false, false><<<gproj, 256>>>(y, Wv, nullptr, nullptr, Vp);

    // Attention
    attn_kernel<<<dim3(NN / 64, NB * HH), 256, ATTN_SMEM_BYTES>>>();

    // Output projection: out = O Wp^T + bp
    gemm_nt<false, true><<<gproj, 256>>>(Op, Wp, nullptr, bp, out);
}

// round 2
// speedup vs baseline: 1.0022x; 1.0022x over previous
#include <cuda_runtime.h>

// Problem constants
#define NB 4
#define NN 1024
#define MM 1024
#define CC 768
#define HH 12
#define DD 64
#define ROWS (NB * NN)        // 4096
#define ATT_SCALE 0.125f      // 64^-0.5

// Scratch (static device arrays — allocation-free per harness rules)
__device__ float g_Q[NB * NN * CC];
__device__ float g_K[NB * MM * CC];
__device__ float g_V[NB * MM * CC];
__device__ float g_O[NB * NN * CC];

// ---------------------------------------------------------------------------
// NT GEMM: out[r][c] = sum_k A[r][k] * W[c][k]  (+ rowbias[r]) (+ colbias[c])
// 64x64 tile per block, 256 threads, 4x4 register micro-tile, BK=16.
// ---------------------------------------------------------------------------
template <bool ROWB, bool COLB>
__global__ __launch_bounds__(256) void gemm_nt(
    const float* __restrict__ A, const float* __restrict__ W,
    const float* __restrict__ rowbias, const float* __restrict__ colbias,
    float* __restrict__ out)
{
    __shared__ float As[16][64];
    __shared__ float Bs[16][64];

    const int tid = threadIdx.x;
    const int tx = tid & 15;       // 0..15 -> output col group
    const int ty = tid >> 4;       // 0..15 -> output row group
    const int row0 = blockIdx.x * 64;
    const int col0 = blockIdx.y * 64;

    const int lm  = tid >> 2;      // 0..63 : tile row being loaded
    const int lk4 = tid & 3;       // 0..3  : float4 index within BK=16

    const float* Ap = A + (size_t)(row0 + lm) * CC + lk4 * 4;
    const float* Wp = W + (size_t)(col0 + lm) * CC + lk4 * 4;

    float acc[4][4] = {};

    for (int k0 = 0; k0 < CC; k0 += 16) {
        float4 av = *(const float4*)(Ap + k0);
        float4 wv = *(const float4*)(Wp + k0);
        As[lk4 * 4 + 0][lm] = av.x;
        As[lk4 * 4 + 1][lm] = av.y;
        As[lk4 * 4 + 2][lm] = av.z;
        As[lk4 * 4 + 3][lm] = av.w;
        Bs[lk4 * 4 + 0][lm] = wv.x;
        Bs[lk4 * 4 + 1][lm] = wv.y;
        Bs[lk4 * 4 + 2][lm] = wv.z;
        Bs[lk4 * 4 + 3][lm] = wv.w;
        __syncthreads();

        #pragma unroll
        for (int k = 0; k < 16; k++) {
            float4 a4 = *(const float4*)&As[k][ty * 4];
            float4 b4 = *(const float4*)&Bs[k][tx * 4];
            float af[4] = {a4.x, a4.y, a4.z, a4.w};
            float bf[4] = {b4.x, b4.y, b4.z, b4.w};
            #pragma unroll
            for (int i = 0; i < 4; i++)
                #pragma unroll
                for (int j = 0; j < 4; j++)
                    acc[i][j] += af[i] * bf[j];
        }
        __syncthreads();
    }

    #pragma unroll
    for (int i = 0; i < 4; i++) {
        const int r = row0 + ty * 4 + i;
        const float rb = ROWB ? rowbias[r] : 0.0f;
        float4 ov;
        const int c = col0 + tx * 4;
        ov.x = acc[i][0] + rb + (COLB ? colbias[c + 0] : 0.0f);
        ov.y = acc[i][1] + rb + (COLB ? colbias[c + 1] : 0.0f);
        ov.z = acc[i][2] + rb + (COLB ? colbias[c + 2] : 0.0f);
        ov.w = acc[i][3] + rb + (COLB ? colbias[c + 3] : 0.0f);
        *(float4*)(out + (size_t)r * CC + c) = ov;
    }
}

// ---------------------------------------------------------------------------
// Flash attention over one (b, h, 64-query tile).
// grid: (NN/64, NB*HH), 256 threads.
// Smem: Qs[d][r] 64x64, Ks[d][c] 64x64, Vs[m][d] 64x64, St[c][r] 64x68 (S^T),
//       alpha/rowmax/rowsum[64].
// ---------------------------------------------------------------------------
#define STS 68   // padded stride for S^T: stride%32==4 (bank spread), 16B aligned

#define ATTN_SMEM_FLOATS (3 * 64 * 64 + 64 * STS + 3 * 64)
#define ATTN_SMEM_BYTES (ATTN_SMEM_FLOATS * 4)

__global__ __launch_bounds__(256) void attn_kernel()
{
    extern __shared__ float sm[];
    float* Qs   = sm;                    // [64][64], Qs[d*64 + r]
    float* Ks   = Qs + 64 * 64;          // [64][64], Ks[d*64 + c]
    float* Vs   = Ks + 64 * 64;          // [64][64], Vs[m*64 + d]
    float* St   = Vs + 64 * 64;          // [64][STS], St[c*STS + r]  (S transposed)
    float* alph = St + 64 * STS;
    float* rmax = alph + 64;
    float* rsum = rmax + 64;

    const int tid = threadIdx.x;
    const int tx = tid & 15;
    const int ty = tid >> 4;
    const int n0 = blockIdx.x * 64;
    const int b  = blockIdx.y / HH;
    const int h  = blockIdx.y % HH;

    const size_t baseQ  = ((size_t)(b * NN + n0)) * CC + h * DD;
    const size_t baseKV = ((size_t)(b * MM)) * CC + h * DD;

    // Load Q tile transposed: Qs[d][r]
    for (int f = tid; f < 1024; f += 256) {
        const int r = f >> 4, d4 = f & 15;
        float4 v = *(const float4*)(g_Q + baseQ + (size_t)r * CC + d4 * 4);
        Qs[(d4 * 4 + 0) * 64 + r] = v.x;
        Qs[(d4 * 4 + 1) * 64 + r] = v.y;
        Qs[(d4 * 4 + 2) * 64 + r] = v.z;
        Qs[(d4 * 4 + 3) * 64 + r] = v.w;
    }
    if (tid < 64) { rmax[tid] = -1e30f; rsum[tid] = 0.0f; }

    float acc[4][4] = {};
    __syncthreads();

    for (int m0 = 0; m0 < MM; m0 += 64) {
        // Load K tile transposed (Ks[d][c]) and V tile natural (Vs[m][d])
        for (int f = tid; f < 1024; f += 256) {
            const int r = f >> 4, d4 = f & 15;
            const size_t g = baseKV + (size_t)(m0 + r) * CC + d4 * 4;
            float4 kv = *(const float4*)(g_K + g);
            Ks[(d4 * 4 + 0) * 64 + r] = kv.x;
            Ks[(d4 * 4 + 1) * 64 + r] = kv.y;
            Ks[(d4 * 4 + 2) * 64 + r] = kv.z;
            Ks[(d4 * 4 + 3) * 64 + r] = kv.w;
            float4 vv = *(const float4*)(g_V + g);
            *(float4*)&Vs[r * 64 + d4 * 4] = vv;
        }
        __syncthreads();

        // S = (Q K^T) * scale, stored transposed into St[c][r]
        {
            float s[4][4] = {};
            #pragma unroll
            for (int d = 0; d < 64; d++) {
                float4 a4 = *(const float4*)&Qs[d * 64 + ty * 4];
                float4 b4 = *(const float4*)&Ks[d * 64 + tx * 4];
                float af[4] = {a4.x, a4.y, a4.z, a4.w};
                float bf[4] = {b4.x, b4.y, b4.z, b4.w};
                #pragma unroll
                for (int i = 0; i < 4; i++)
                    #pragma unroll
                    for (int j = 0; j < 4; j++)
                        s[i][j] += af[i] * bf[j];
            }
            #pragma unroll
            for (int i = 0; i < 4; i++)
                #pragma unroll
                for (int j = 0; j < 4; j++)
                    St[(tx * 4 + j) * STS + (ty * 4 + i)] = s[i][j] * ATT_SCALE;
        }
        __syncthreads();

        // Online softmax row pass: thread t owns row t (reads column t of St)
        if (tid < 64) {
            const int r = tid;
            const float mo = rmax[r];
            float ml = -1e30f;
            #pragma unroll 8
            for (int m = 0; m < 64; m++) ml = fmaxf(ml, St[m * STS + r]);
            const float mn = fmaxf(mo, ml);
            const float al = __expf(mo - mn);
            float ssum = 0.0f;
            #pragma unroll 8
            for (int m = 0; m < 64; m++) {
                const float p = __expf(St[m * STS + r] - mn);
                St[m * STS + r] = p;
                ssum += p;
            }
            rsum[r] = rsum[r] * al + ssum;
            rmax[r] = mn;
            alph[r] = al;
        }
        __syncthreads();

        // O = O * alpha(row) + P @ V
        {
            float al[4];
            #pragma unroll
            for (int i = 0; i < 4; i++) al[i] = alph[ty * 4 + i];
            #pragma unroll
            for (int i = 0; i < 4; i++)
                #pragma unroll
                for (int j = 0; j < 4; j++)
                    acc[i][j] *= al[i];

            #pragma unroll
            for (int m = 0; m < 64; m++) {
                float4 p4 = *(const float4*)&St[m * STS + ty * 4];
                float4 v4 = *(const float4*)&Vs[m * 64 + tx * 4];
                float pf[4] = {p4.x, p4.y, p4.z, p4.w};
                float vf[4] = {v4.x, v4.y, v4.z, v4.w};
                #pragma unroll
                for (int i = 0; i < 4; i++)
                    #pragma unroll
                    for (int j = 0; j < 4; j++)
                        acc[i][j] += pf[i] * vf[j];
            }
        }
        __syncthreads();
    }

    // Normalize and write out (same layout as Q: [b, n, h*D + d])
    float inv[4];
    #pragma unroll
    for (int i = 0; i < 4; i++) inv[i] = 1.0f / rsum[ty * 4 + i];
    #pragma unroll
    for (int i = 0; i < 4; i++) {
        const size_t o = baseQ + (size_t)(ty * 4 + i) * CC + tx * 4;
        float4 ov;
        ov.x = acc[i][0] * inv[i];
        ov.y = acc[i][1] * inv[i];
        ov.z = acc[i][2] * inv[i];
        ov.w = acc[i][3] * inv[i];
        *(float4*)(g_O + o) = ov;
    }
}

// ---------------------------------------------------------------------------
// Launch
// ---------------------------------------------------------------------------
extern "C" void kernel_launch(void* const* d_in, const int* in_sizes, int n_in,
                              void* d_out, int out_size)
{
    const float* x  = (const float*)d_in[0];
    const float* y  = (const float*)d_in[1];
    const float* yw = (const float*)d_in[2];
    const float* Wq = (const float*)d_in[3];
    const float* Wk = (const float*)d_in[4];
    const float* Wv = (const float*)d_in[5];
    const float* Wp = (const float*)d_in[6];
    const float* bp = (const float*)d_in[7];
    float* out = (float*)d_out;

    float *Qp, *Kp, *Vp, *Op;
    cudaGetSymbolAddress((void**)&Qp, g_Q);
    cudaGetSymbolAddress((void**)&Kp, g_K);
    cudaGetSymbolAddress((void**)&Vp, g_V);
    cudaGetSymbolAddress((void**)&Op, g_O);

    cudaFuncSetAttribute(attn_kernel,
                         cudaFuncAttributeMaxDynamicSharedMemorySize,
                         ATTN_SMEM_BYTES);

    const dim3 gproj(ROWS / 64, CC / 64);

    // Projections: Q = x Wq^T ; K = y Wk^T + yw[r] ; V = y Wv^T
    gemm_nt<false, false><<<gproj, 256>>>(x, Wq, nullptr, nullptr, Qp);
    gemm_nt<true,  false><<<gproj, 256>>>(y, Wk, yw,      nullptr, Kp);
    gemm_nt<false, false><<<gproj, 256>>>(y, Wv, nullptr, nullptr, Vp);

    // Attention
    attn_kernel<<<dim3(NN / 64, NB * HH), 256, ATTN_SMEM_BYTES>>>();

    // Output projection: out = O Wp^T + bp
    gemm_nt<false, true><<<gproj, 256>>>(Op, Wp, nullptr, bp, out);
}

// round 4
// speedup vs baseline: 2.6050x; 2.5991x over previous
#include <cuda_runtime.h>
#include <cuda_bf16.h>
#include <cstdint>

// Problem constants
#define NB 4
#define NN 1024
#define MM 1024
#define CC 768
#define HH 12
#define DD 64
#define ROWS (NB * NN)        // 4096
#define ATT_SCALE 0.125f      // 64^-0.5

#define GSTRIDE 72            // padded bf16 row stride in smem (144B, 16B-multiple)

// ---------------------------------------------------------------------------
// Scratch (static device arrays — allocation-free per harness rules)
// ---------------------------------------------------------------------------
__device__ __nv_bfloat16 g_xh[ROWS * CC], g_xl[ROWS * CC];
__device__ __nv_bfloat16 g_yh[ROWS * CC], g_yl[ROWS * CC];
__device__ __nv_bfloat16 g_qh[ROWS * CC], g_ql[ROWS * CC];
__device__ __nv_bfloat16 g_kh[ROWS * CC], g_kl[ROWS * CC];
__device__ __nv_bfloat16 g_vh[ROWS * CC], g_vl[ROWS * CC];
__device__ __nv_bfloat16 g_oh[ROWS * CC], g_ol[ROWS * CC];
__device__ __nv_bfloat16 g_wqh[CC * CC], g_wql[CC * CC];
__device__ __nv_bfloat16 g_wkh[CC * CC], g_wkl[CC * CC];
__device__ __nv_bfloat16 g_wvh[CC * CC], g_wvl[CC * CC];
__device__ __nv_bfloat16 g_wph[CC * CC], g_wpl[CC * CC];

// ---------------------------------------------------------------------------
// Helpers
// ---------------------------------------------------------------------------
__device__ __forceinline__ uint32_t smem_u32(const void* p) {
    uint32_t a;
    asm("{ .reg .u64 t; cvta.to.shared.u64 t, %1; cvt.u32.u64 %0, t; }"
        : "=r"(a) : "l"(p));
    return a;
}

// D += A * B  (m16n8k16, bf16 in, fp32 accum)
__device__ __forceinline__ void mma16816(float d[4],
    uint32_t a0, uint32_t a1, uint32_t a2, uint32_t a3,
    uint32_t b0, uint32_t b1)
{
    asm volatile(
        "mma.sync.aligned.m16n8k16.row.col.f32.bf16.bf16.f32 "
        "{%0,%1,%2,%3}, {%4,%5,%6,%7}, {%8,%9}, {%0,%1,%2,%3};"
        : "+f"(d[0]), "+f"(d[1]), "+f"(d[2]), "+f"(d[3])
        : "r"(a0), "r"(a1), "r"(a2), "r"(a3), "r"(b0), "r"(b1));
}

__device__ __forceinline__ void ldsm4(uint32_t r[4], uint32_t addr) {
    asm volatile("ldmatrix.sync.aligned.m8n8.x4.shared.b16 {%0,%1,%2,%3}, [%4];"
                 : "=r"(r[0]), "=r"(r[1]), "=r"(r[2]), "=r"(r[3]) : "r"(addr));
}
__device__ __forceinline__ void ldsm4t(uint32_t r[4], uint32_t addr) {
    asm volatile("ldmatrix.sync.aligned.m8n8.x4.trans.shared.b16 {%0,%1,%2,%3}, [%4];"
                 : "=r"(r[0]), "=r"(r[1]), "=r"(r[2]), "=r"(r[3]) : "r"(addr));
}

// Split two fp32 into packed bf16-hi (truncation) + bf16-lo (rounded residual)
__device__ __forceinline__ void pack_split(float v0, float v1,
                                           uint32_t& hp, uint32_t& lp)
{
    const uint32_t u0 = __float_as_uint(v0), u1 = __float_as_uint(v1);
    hp = __byte_perm(u0, u1, 0x7632);   // low16 = hi(v0), high16 = hi(v1)
    const float r0 = v0 - __uint_as_float(u0 & 0xFFFF0000u);
    const float r1 = v1 - __uint_as_float(u1 & 0xFFFF0000u);
    __nv_bfloat162 t = __floats2bfloat162_rn(r0, r1);
    lp = *reinterpret_cast<uint32_t*>(&t);
}

__device__ __forceinline__ void split_store(__nv_bfloat16* H, __nv_bfloat16* L,
                                            size_t off, float v0, float v1)
{
    uint32_t hp, lp;
    pack_split(v0, v1, hp, lp);
    *reinterpret_cast<uint32_t*>(H + off) = hp;
    *reinterpret_cast<uint32_t*>(L + off) = lp;
}

// ---------------------------------------------------------------------------
// fp32 -> (bf16 hi, bf16 lo) split
// ---------------------------------------------------------------------------
__global__ __launch_bounds__(256) void cvt_split(
    const float* __restrict__ s, __nv_bfloat16* __restrict__ h,
    __nv_bfloat16* __restrict__ l, int n)
{
    int i = blockIdx.x * blockDim.x + threadIdx.x;
    const int stride = gridDim.x * blockDim.x;
    for (; i < n; i += stride) {
        const float v = s[i];
        const __nv_bfloat16 hb = __float2bfloat16(v);
        h[i] = hb;
        l[i] = __float2bfloat16(v - __bfloat162float(hb));
    }
}

// ---------------------------------------------------------------------------
// mma.sync NT GEMM with bf16 hi/lo:
//   C[r][c] = sum_k A[r][k] * W[c][k]  (+ rowbias[r]) (+ colbias[c])
// CTA tile 128x128, BK=64, 8 warps (2m x 4n), warp tile 64x32.
// SPLIT: write bf16 hi/lo pair arrays; else write fp32.
// ---------------------------------------------------------------------------
#define GEMM_SMEM (4 * 128 * GSTRIDE * 2)   // Ah, Al, Bh, Bl = 73728 B

template <bool ROWB, bool COLB, bool SPLIT>
__global__ __launch_bounds__(256) void gemm_ms(
    const __nv_bfloat16* __restrict__ Ah, const __nv_bfloat16* __restrict__ Al,
    const __nv_bfloat16* __restrict__ Bh, const __nv_bfloat16* __restrict__ Bl,
    const float* __restrict__ rowbias, const float* __restrict__ colbias,
    float* __restrict__ outF,
    __nv_bfloat16* __restrict__ outH, __nv_bfloat16* __restrict__ outL)
{
    extern __shared__ char sm[];
    __nv_bfloat16* sA = (__nv_bfloat16*)sm;     // [hi|lo] each 128 x GSTRIDE
    const uint32_t sbase = smem_u32(sm);

    const int tid = threadIdx.x;
    const int wid = tid >> 5, lane = tid & 31;
    const int wm = wid >> 2, wn = wid & 3;      // 2 x 4 warp grid
    const int lrow = lane & 15, lcol = (lane >> 4) * 8;
    const int row0 = blockIdx.x * 128;
    const int col0 = blockIdx.y * 128;

    const __nv_bfloat16* srcs[4] = {Ah, Al, Bh, Bl};
    const int rbase[4] = {row0, row0, col0, col0};

    float acc[4][4][4];
    #pragma unroll
    for (int i = 0; i < 4; i++)
        #pragma unroll
        for (int j = 0; j < 4; j++)
            #pragma unroll
            for (int e = 0; e < 4; e++) acc[i][j][e] = 0.0f;

    // per-warp ldmatrix base offsets (bytes)
    const uint32_t aAh = sbase + ((wm * 64 + lrow) * GSTRIDE + lcol) * 2;
    const uint32_t aAl = aAh + 128 * GSTRIDE * 2;
    const uint32_t aBh = sbase + (2 * 128 * GSTRIDE + (wn * 32 + lrow) * GSTRIDE + lcol) * 2;
    const uint32_t aBl = aBh + 128 * GSTRIDE * 2;

    for (int st = 0; st < CC / 64; st++) {
        const int k0 = st * 64;
        // load 4 tiles of 128 rows x 64 bf16
        #pragma unroll
        for (int a = 0; a < 4; a++) {
            #pragma unroll
            for (int j = 0; j < 4; j++) {
                const int i = tid + j * 256;
                const int r = i >> 3, c = i & 7;
                *(uint4*)(sA + a * 128 * GSTRIDE + r * GSTRIDE + c * 8) =
                    *(const uint4*)(srcs[a] + (size_t)(rbase[a] + r) * CC + k0 + c * 8);
            }
        }
        __syncthreads();

        #pragma unroll
        for (int kk = 0; kk < 4; kk++) {
            uint32_t afh[4][4], afl[4][4];
            #pragma unroll
            for (int mt = 0; mt < 4; mt++) {
                ldsm4(afh[mt], aAh + (mt * 16 * GSTRIDE + kk * 16) * 2);
                ldsm4(afl[mt], aAl + (mt * 16 * GSTRIDE + kk * 16) * 2);
            }
            #pragma unroll
            for (int ng = 0; ng < 2; ng++) {
                uint32_t bh[4], bl[4];
                ldsm4(bh, aBh + (ng * 16 * GSTRIDE + kk * 16) * 2);
                ldsm4(bl, aBl + (ng * 16 * GSTRIDE + kk * 16) * 2);
                #pragma unroll
                for (int mt = 0; mt < 4; mt++) {
                    // n-tile 2*ng : {bh[0], bh[2]}
                    mma16816(acc[mt][2 * ng], afh[mt][0], afh[mt][1], afh[mt][2], afh[mt][3], bh[0], bh[2]);
                    mma16816(acc[mt][2 * ng], afh[mt][0], afh[mt][1], afh[mt][2], afh[mt][3], bl[0], bl[2]);
                    mma16816(acc[mt][2 * ng], afl[mt][0], afl[mt][1], afl[mt][2], afl[mt][3], bh[0], bh[2]);
                    // n-tile 2*ng+1 : {bh[1], bh[3]}
                    mma16816(acc[mt][2 * ng + 1], afh[mt][0], afh[mt][1], afh[mt][2], afh[mt][3], bh[1], bh[3]);
                    mma16816(acc[mt][2 * ng + 1], afh[mt][0], afh[mt][1], afh[mt][2], afh[mt][3], bl[1], bl[3]);
                    mma16816(acc[mt][2 * ng + 1], afl[mt][0], afl[mt][1], afl[mt][2], afl[mt][3], bh[1], bh[3]);
                }
            }
        }
        __syncthreads();
    }

    // Epilogue
    #pragma unroll
    for (int mt = 0; mt < 4; mt++) {
        const int r_lo = row0 + wm * 64 + mt * 16 + (lane >> 2);
        const int r_hi = r_lo + 8;
        const float rb_lo = ROWB ? rowbias[r_lo] : 0.0f;
        const float rb_hi = ROWB ? rowbias[r_hi] : 0.0f;
        #pragma unroll
        for (int nt = 0; nt < 4; nt++) {
            const int c = col0 + wn * 32 + nt * 8 + 2 * (lane & 3);
            const float cb0 = COLB ? colbias[c] : 0.0f;
            const float cb1 = COLB ? colbias[c + 1] : 0.0f;
            const float v0 = acc[mt][nt][0] + rb_lo + cb0;
            const float v1 = acc[mt][nt][1] + rb_lo + cb1;
            const float v2 = acc[mt][nt][2] + rb_hi + cb0;
            const float v3 = acc[mt][nt][3] + rb_hi + cb1;
            if (SPLIT) {
                split_store(outH, outL, (size_t)r_lo * CC + c, v0, v1);
                split_store(outH, outL, (size_t)r_hi * CC + c, v2, v3);
            } else {
                *(float2*)(outF + (size_t)r_lo * CC + c) = make_float2(v0, v1);
                *(float2*)(outF + (size_t)r_hi * CC + c) = make_float2(v2, v3);
            }
        }
    }
}

// ---------------------------------------------------------------------------
// Flash attention (mma.sync, bf16 hi/lo), FA2-style.
// grid (NN/128, NB*HH), 256 threads; warp owns 16 q-rows; key blocks of 64.
// ---------------------------------------------------------------------------
#define ATT_SMEM (2 * 128 * GSTRIDE * 2)    // == 4 * 64 * GSTRIDE * 2 = 36864 B

__global__ __launch_bounds__(256) void attn_ms()
{
    extern __shared__ char sm[];
    const uint32_t sbase = smem_u32(sm);

    const int tid = threadIdx.x;
    const int wid = tid >> 5, lane = tid & 31;
    const int lrow = lane & 15, lcol = (lane >> 4) * 8;
    const int n0 = blockIdx.x * 128;
    const int b = blockIdx.y / HH, h = blockIdx.y % HH;
    const size_t qrow0 = (size_t)(b * NN + n0);
    const size_t kvrow0 = (size_t)(b * MM);

    // ---- Phase A: Q tile -> smem, then Q frags to registers ----
    {
        __nv_bfloat16* sQh = (__nv_bfloat16*)sm;
        __nv_bfloat16* sQl = sQh + 128 * GSTRIDE;
        #pragma unroll
        for (int j = 0; j < 4; j++) {
            const int i = tid + j * 256;
            const int r = i >> 3, c = i & 7;
            const size_t g = (qrow0 + r) * CC + h * DD + c * 8;
            *(uint4*)(sQh + r * GSTRIDE + c * 8) = *(const uint4*)(g_qh + g);
            *(uint4*)(sQl + r * GSTRIDE + c * 8) = *(const uint4*)(g_ql + g);
        }
    }
    __syncthreads();

    uint32_t qfh[4][4], qfl[4][4];
    {
        const uint32_t qb = sbase + ((wid * 16 + lrow) * GSTRIDE + lcol) * 2;
        #pragma unroll
        for (int kk = 0; kk < 4; kk++) {
            ldsm4(qfh[kk], qb + kk * 32);
            ldsm4(qfl[kk], qb + 128 * GSTRIDE * 2 + kk * 32);
        }
    }
    __syncthreads();

    // online softmax state (2 rows per thread) + O accum
    float m0 = -1e30f, m1 = -1e30f, l0 = 0.0f, l1 = 0.0f;
    float o[8][4];
    #pragma unroll
    for (int dt = 0; dt < 8; dt++)
        #pragma unroll
        for (int e = 0; e < 4; e++) o[dt][e] = 0.0f;

    __nv_bfloat16* skv = (__nv_bfloat16*)sm;    // [kh|kl|vh|vl], each 64 x GSTRIDE
    const uint32_t kA = sbase + (lrow * GSTRIDE + lcol) * 2;
    const uint32_t vA = sbase + (2 * 64 * GSTRIDE + lrow * GSTRIDE + lcol) * 2;
    const uint32_t LOFS = 64 * GSTRIDE * 2;     // hi->lo byte offset

    for (int m0i = 0; m0i < MM; m0i += 64) {
        // load K/V hi/lo block (64 x 64 each)
        {
            const __nv_bfloat16* gk[4] = {g_kh, g_kl, g_vh, g_vl};
            #pragma unroll
            for (int a = 0; a < 4; a++) {
                #pragma unroll
                for (int j = 0; j < 2; j++) {
                    const int i = tid + j * 256;
                    const int r = i >> 3, c = i & 7;
                    *(uint4*)(skv + a * 64 * GSTRIDE + r * GSTRIDE + c * 8) =
                        *(const uint4*)(gk[a] + (kvrow0 + m0i + r) * CC + h * DD + c * 8);
                }
            }
        }
        __syncthreads();

        // ---- S = Q K^T (hi/lo 3-term) ----
        float s[8][4];
        #pragma unroll
        for (int nt = 0; nt < 8; nt++)
            #pragma unroll
            for (int e = 0; e < 4; e++) s[nt][e] = 0.0f;

        #pragma unroll
        for (int kg = 0; kg < 4; kg++) {
            #pragma unroll
            for (int kk = 0; kk < 4; kk++) {
                uint32_t bh[4], bl[4];
                const uint32_t o2 = (kg * 16 * GSTRIDE + kk * 16) * 2;
                ldsm4(bh, kA + o2);
                ldsm4(bl, kA + LOFS + o2);
                mma16816(s[2 * kg], qfh[kk][0], qfh[kk][1], qfh[kk][2], qfh[kk][3], bh[0], bh[2]);
                mma16816(s[2 * kg], qfh[kk][0], qfh[kk][1], qfh[kk][2], qfh[kk][3], bl[0], bl[2]);
                mma16816(s[2 * kg], qfl[kk][0], qfl[kk][1], qfl[kk][2], qfl[kk][3], bh[0], bh[2]);
                mma16816(s[2 * kg + 1], qfh[kk][0], qfh[kk][1], qfh[kk][2], qfh[kk][3], bh[1], bh[3]);
                mma16816(s[2 * kg + 1], qfh[kk][0], qfh[kk][1], qfh[kk][2], qfh[kk][3], bl[1], bl[3]);
                mma16816(s[2 * kg + 1], qfl[kk][0], qfl[kk][1], qfl[kk][2], qfl[kk][3], bh[1], bh[3]);
            }
        }

        // ---- online softmax (rows t/4 and t/4+8, cols spread over t%4 quad) ----
        #pragma unroll
        for (int nt = 0; nt < 8; nt++)
            #pragma unroll
            for (int e = 0; e < 4; e++) s[nt][e] *= ATT_SCALE;

        float mx0 = -1e30f, mx1 = -1e30f;
        #pragma unroll
        for (int nt = 0; nt < 8; nt++) {
            mx0 = fmaxf(mx0, fmaxf(s[nt][0], s[nt][1]));
            mx1 = fmaxf(mx1, fmaxf(s[nt][2], s[nt][3]));
        }
        mx0 = fmaxf(mx0, __shfl_xor_sync(0xFFFFFFFFu, mx0, 1));
        mx0 = fmaxf(mx0, __shfl_xor_sync(0xFFFFFFFFu, mx0, 2));
        mx1 = fmaxf(mx1, __shfl_xor_sync(0xFFFFFFFFu, mx1, 1));
        mx1 = fmaxf(mx1, __shfl_xor_sync(0xFFFFFFFFu, mx1, 2));

        const float mn0 = fmaxf(m0, mx0), mn1 = fmaxf(m1, mx1);
        const float a0 = __expf(m0 - mn0), a1 = __expf(m1 - mn1);
        m0 = mn0; m1 = mn1;

        float sum0 = 0.0f, sum1 = 0.0f;
        #pragma unroll
        for (int nt = 0; nt < 8; nt++) {
            s[nt][0] = __expf(s[nt][0] - mn0); sum0 += s[nt][0];
            s[nt][1] = __expf(s[nt][1] - mn0); sum0 += s[nt][1];
            s[nt][2] = __expf(s[nt][2] - mn1); sum1 += s[nt][2];
            s[nt][3] = __expf(s[nt][3] - mn1); sum1 += s[nt][3];
        }
        sum0 += __shfl_xor_sync(0xFFFFFFFFu, sum0, 1);
        sum0 += __shfl_xor_sync(0xFFFFFFFFu, sum0, 2);
        sum1 += __shfl_xor_sync(0xFFFFFFFFu, sum1, 1);
        sum1 += __shfl_xor_sync(0xFFFFFFFFu, sum1, 2);
        l0 = l0 * a0 + sum0;
        l1 = l1 * a1 + sum1;

        #pragma unroll
        for (int dt = 0; dt < 8; dt++) {
            o[dt][0] *= a0; o[dt][1] *= a0;
            o[dt][2] *= a1; o[dt][3] *= a1;
        }

        // ---- P -> bf16 hi/lo A-frags ----
        uint32_t ph[4][4], pl[4][4];
        #pragma unroll
        for (int kg = 0; kg < 4; kg++) {
            pack_split(s[2 * kg][0], s[2 * kg][1], ph[kg][0], pl[kg][0]);
            pack_split(s[2 * kg][2], s[2 * kg][3], ph[kg][1], pl[kg][1]);
            pack_split(s[2 * kg + 1][0], s[2 * kg + 1][1], ph[kg][2], pl[kg][2]);
            pack_split(s[2 * kg + 1][2], s[2 * kg + 1][3], ph[kg][3], pl[kg][3]);
        }

        // ---- O += P V (hi/lo 3-term), V via ldmatrix.trans ----
        #pragma unroll
        for (int kg = 0; kg < 4; kg++) {
            #pragma unroll
            for (int dg = 0; dg < 4; dg++) {
                uint32_t vh4[4], vl4[4];
                const uint32_t o2 = (kg * 16 * GSTRIDE + dg * 16) * 2;
                ldsm4t(vh4, vA + o2);
                ldsm4t(vl4, vA + LOFS + o2);
                mma16816(o[2 * dg], ph[kg][0], ph[kg][1], ph[kg][2], ph[kg][3], vh4[0], vh4[1]);
                mma16816(o[2 * dg], ph[kg][0], ph[kg][1], ph[kg][2], ph[kg][3], vl4[0], vl4[1]);
                mma16816(o[2 * dg], pl[kg][0], pl[kg][1], pl[kg][2], pl[kg][3], vh4[0], vh4[1]);
                mma16816(o[2 * dg + 1], ph[kg][0], ph[kg][1], ph[kg][2], ph[kg][3], vh4[2], vh4[3]);
                mma16816(o[2 * dg + 1], ph[kg][0], ph[kg][1], ph[kg][2], ph[kg][3], vl4[2], vl4[3]);
                mma16816(o[2 * dg + 1], pl[kg][0], pl[kg][1], pl[kg][2], pl[kg][3], vh4[2], vh4[3]);
            }
        }
        __syncthreads();
    }

    // ---- normalize + split-store O ----
    const float inv0 = 1.0f / l0, inv1 = 1.0f / l1;
    const size_t r_lo = qrow0 + wid * 16 + (lane >> 2);
    const size_t r_hi = r_lo + 8;
    #pragma unroll
    for (int dt = 0; dt < 8; dt++) {
        const int c = h * DD + dt * 8 + 2 * (lane & 3);
        split_store(g_oh, g_ol, r_lo * CC + c, o[dt][0] * inv0, o[dt][1] * inv0);
        split_store(g_oh, g_ol, r_hi * CC + c, o[dt][2] * inv1, o[dt][3] * inv1);
    }
}

// ---------------------------------------------------------------------------
// Launch
// ---------------------------------------------------------------------------
extern "C" void kernel_launch(void* const* d_in, const int* in_sizes, int n_in,
                              void* d_out, int out_size)
{
    const float* x  = (const float*)d_in[0];
    const float* y  = (const float*)d_in[1];
    const float* yw = (const float*)d_in[2];
    const float* Wq = (const float*)d_in[3];
    const float* Wk = (const float*)d_in[4];
    const float* Wv = (const float*)d_in[5];
    const float* Wp = (const float*)d_in[6];
    const float* bp = (const float*)d_in[7];
    float* out = (float*)d_out;

    __nv_bfloat16 *xh, *xl, *yh, *yl, *oh, *ol;
    __nv_bfloat16 *qh, *ql, *kh, *kl, *vh, *vl;
    __nv_bfloat16 *wqh, *wql, *wkh, *wkl, *wvh, *wvl, *wph, *wpl;
    cudaGetSymbolAddress((void**)&xh, g_xh);   cudaGetSymbolAddress((void**)&xl, g_xl);
    cudaGetSymbolAddress((void**)&yh, g_yh);   cudaGetSymbolAddress((void**)&yl, g_yl);
    cudaGetSymbolAddress((void**)&qh, g_qh);   cudaGetSymbolAddress((void**)&ql, g_ql);
    cudaGetSymbolAddress((void**)&kh, g_kh);   cudaGetSymbolAddress((void**)&kl, g_kl);
    cudaGetSymbolAddress((void**)&vh, g_vh);   cudaGetSymbolAddress((void**)&vl, g_vl);
    cudaGetSymbolAddress((void**)&oh, g_oh);   cudaGetSymbolAddress((void**)&ol, g_ol);
    cudaGetSymbolAddress((void**)&wqh, g_wqh); cudaGetSymbolAddress((void**)&wql, g_wql);
    cudaGetSymbolAddress((void**)&wkh, g_wkh); cudaGetSymbolAddress((void**)&wkl, g_wkl);
    cudaGetSymbolAddress((void**)&wvh, g_wvh); cudaGetSymbolAddress((void**)&wvl, g_wvl);
    cudaGetSymbolAddress((void**)&wph, g_wph); cudaGetSymbolAddress((void**)&wpl, g_wpl);

    cudaFuncSetAttribute(gemm_ms<false, false, true>,
                         cudaFuncAttributeMaxDynamicSharedMemorySize, GEMM_SMEM);
    cudaFuncSetAttribute(gemm_ms<true, false, true>,
                         cudaFuncAttributeMaxDynamicSharedMemorySize, GEMM_SMEM);
    cudaFuncSetAttribute(gemm_ms<false, true, false>,
                         cudaFuncAttributeMaxDynamicSharedMemorySize, GEMM_SMEM);
    cudaFuncSetAttribute(attn_ms,
                         cudaFuncAttributeMaxDynamicSharedMemorySize, ATT_SMEM);

    const int nAct = ROWS * CC;   // 3.1M
    const int nW   = CC * CC;     // 0.59M

    cvt_split<<<4096, 256>>>(x,  xh,  xl,  nAct);
    cvt_split<<<4096, 256>>>(y,  yh,  yl,  nAct);
    cvt_split<<<2304, 256>>>(Wq, wqh, wql, nW);
    cvt_split<<<2304, 256>>>(Wk, wkh, wkl, nW);
    cvt_split<<<2304, 256>>>(Wv, wvh, wvl, nW);
    cvt_split<<<2304, 256>>>(Wp, wph, wpl, nW);

    const dim3 gproj(ROWS / 128, CC / 128);   // (32, 6)

    // Projections (tensor cores via mma.sync), outputs pre-split bf16 hi/lo
    gemm_ms<false, false, true><<<gproj, 256, GEMM_SMEM>>>(
        xh, xl, wqh, wql, nullptr, nullptr, nullptr, qh, ql);
    gemm_ms<true, false, true><<<gproj, 256, GEMM_SMEM>>>(
        yh, yl, wkh, wkl, yw, nullptr, nullptr, kh, kl);
    gemm_ms<false, false, true><<<gproj, 256, GEMM_SMEM>>>(
        yh, yl, wvh, wvl, nullptr, nullptr, nullptr, vh, vl);

    // Attention (tensor cores), writes O hi/lo
    attn_ms<<<dim3(NN / 128, NB * HH), 256, ATT_SMEM>>>();

    // Output projection: out = O Wp^T + bp (fp32 out)
    gemm_ms<false, true, false><<<gproj, 256, GEMM_SMEM>>>(
        oh, ol, wph, wpl, nullptr, bp, out, nullptr, nullptr);
}